// round 1
// baseline (speedup 1.0000x reference)
#include <cuda_runtime.h>
#include <math.h>

// Problem constants
#define BATCH 32
#define DEPTH 11
#define NNODES 2047          // 2^11 - 1
#define IND 300
#define MD 300
#define LEAF_BASE 1023       // 2^10 - 1
#define LEAF_CNT 1024
#define TOTAL_ROWS (BATCH * NNODES)   // 65504

// GEMM tile config
#define BM 128
#define BN 128
#define BK 16
#define AS_LD 132            // padded lead dim for transposed A smem

// -------------------- device scratch --------------------
__device__ float g_gates_x[(size_t)TOTAL_ROWS * 1200]; // [row][ix|fx|ox|ux]
__device__ float g_c[(size_t)TOTAL_ROWS * MD];
__device__ float g_iou[(size_t)(BATCH * 512) * 900];   // max level-9 rows x [ih|oh|uh]
__device__ float g_f[(size_t)(2 * BATCH * 512) * 300]; // stacked [f(h1); f(h2)]
__device__ float g_Wx[300 * 1200];
__device__ float g_bx[1200];
__device__ float g_Wh[300 * 900];

__device__ __forceinline__ float sigmoidf(float x) {
    return 1.0f / (1.0f + expf(-x));
}

// -------------------- weight packing --------------------
__global__ void pack_kernel(
    const float* __restrict__ Wix, const float* __restrict__ Wfx,
    const float* __restrict__ Wox, const float* __restrict__ Wux,
    const float* __restrict__ bix, const float* __restrict__ bfx,
    const float* __restrict__ box_, const float* __restrict__ bux,
    const float* __restrict__ Wih, const float* __restrict__ Woh,
    const float* __restrict__ Wuh)
{
    int i = blockIdx.x * blockDim.x + threadIdx.x;
    if (i < 300 * 1200) {
        int k = i / 1200, cj = i % 1200;
        int g = cj / 300, j = cj % 300;
        const float* W = (g == 0) ? Wix : (g == 1) ? Wfx : (g == 2) ? Wox : Wux;
        g_Wx[i] = W[k * 300 + j];
    }
    if (i < 1200) {
        int g = i / 300, j = i % 300;
        const float* bb = (g == 0) ? bix : (g == 1) ? bfx : (g == 2) ? box_ : bux;
        g_bx[i] = bb[j];
    }
    if (i < 300 * 900) {
        int k = i / 900, cj = i % 900;
        int g = cj / 300, j = cj % 300;
        const float* W = (g == 0) ? Wih : (g == 1) ? Woh : Wuh;
        g_Wh[i] = W[k * 300 + j];
    }
}

// -------------------- generic SGEMM with fused A-gather --------------------
// mode 0: A plain  (row r -> A + r*lda)
// mode 1: A = h[child1] + h[child2] for level `level_l` (A points at h base)
// mode 2: A = h[child1] for rows [0,Mh), h[child2] for rows [Mh,2Mh)
__global__ __launch_bounds__(256) void gemm_kernel(
    const float* __restrict__ A, const float* __restrict__ Bm,
    float* __restrict__ C, const float* __restrict__ bias,
    int M, int N, int K, int lda, int ldb, int ldc,
    int mode, int level_l)
{
    __shared__ __align__(16) float As[BK][AS_LD];
    __shared__ __align__(16) float Bs[BK][BN];

    const int tid = threadIdx.x;
    const int m_base = blockIdx.y * BM;
    const int n_base = blockIdx.x * BN;

    // ---- A tile load mapping: thread -> (row am, k half ak) ----
    const int am = tid >> 1;
    const int ak = (tid & 1) * 8;
    const float* arow1 = nullptr;
    const float* arow2 = nullptr;
    const int grow = m_base + am;
    const bool arow_ok = (grow < M);
    if (arow_ok) {
        if (mode == 0) {
            arow1 = A + (size_t)grow * lda;
        } else {
            const int nl = 1 << level_l;
            const int Mh = BATCH << level_l;
            int rr = grow, sel = 0;
            if (mode == 2 && grow >= Mh) { sel = 1; rr = grow - Mh; }
            const int b = rr >> level_l;
            const int t = rr & (nl - 1);
            const int node = (nl - 1) + t;
            if (mode == 1) {
                arow1 = A + ((size_t)b * NNODES + 2 * node + 1) * MD;
                arow2 = A + ((size_t)b * NNODES + 2 * node + 2) * MD;
            } else {
                arow1 = A + ((size_t)b * NNODES + 2 * node + 1 + sel) * MD;
            }
        }
    }

    // ---- B tile load mapping ----
    const int bk = tid >> 4;
    const int bn = (tid & 15) * 8;

    // ---- microtile mapping ----
    const int ty = tid >> 4, tx = tid & 15;
    const int mr = ty * 8, nr = tx * 8;

    float acc[8][8];
#pragma unroll
    for (int i = 0; i < 8; i++)
#pragma unroll
        for (int j = 0; j < 8; j++) acc[i][j] = 0.0f;

    for (int k0 = 0; k0 < K; k0 += BK) {
        // stage A into registers
        float av[8];
#pragma unroll
        for (int j = 0; j < 8; j++) {
            const int kk = k0 + ak + j;
            float v = 0.0f;
            if (arow_ok && kk < K) {
                v = __ldg(arow1 + kk);
                if (mode == 1) v += __ldg(arow2 + kk);
            }
            av[j] = v;
        }
        // stage B into registers
        float bv[8];
        const int kb = k0 + bk;
        const bool kb_ok = (kb < K);
#pragma unroll
        for (int j = 0; j < 8; j++) {
            const int nn = n_base + bn + j;
            bv[j] = (kb_ok && nn < N) ? __ldg(Bm + (size_t)kb * ldb + nn) : 0.0f;
        }
        __syncthreads();
#pragma unroll
        for (int j = 0; j < 8; j++) As[ak + j][am] = av[j];
#pragma unroll
        for (int j = 0; j < 8; j++) Bs[bk][bn + j] = bv[j];
        __syncthreads();

#pragma unroll
        for (int kk = 0; kk < BK; kk++) {
            float4 a0 = *(const float4*)&As[kk][mr];
            float4 a1 = *(const float4*)&As[kk][mr + 4];
            float4 b0 = *(const float4*)&Bs[kk][nr];
            float4 b1 = *(const float4*)&Bs[kk][nr + 4];
            float a[8] = {a0.x, a0.y, a0.z, a0.w, a1.x, a1.y, a1.z, a1.w};
            float b[8] = {b0.x, b0.y, b0.z, b0.w, b1.x, b1.y, b1.z, b1.w};
#pragma unroll
            for (int i = 0; i < 8; i++)
#pragma unroll
                for (int j = 0; j < 8; j++)
                    acc[i][j] = fmaf(a[i], b[j], acc[i][j]);
        }
    }

    // ---- epilogue ----
#pragma unroll
    for (int i = 0; i < 8; i++) {
        const int gm = m_base + mr + i;
        if (gm >= M) continue;
        float* crow = C + (size_t)gm * ldc;
#pragma unroll
        for (int j = 0; j < 8; j++) {
            const int gn = n_base + nr + j;
            if (gn < N) {
                float v = acc[i][j];
                if (bias) v += bias[gn];
                crow[gn] = v;
            }
        }
    }
}

// -------------------- pointwise: leaves --------------------
__global__ void leaf_kernel(float* __restrict__ h,
                            const float* __restrict__ bih,
                            const float* __restrict__ boh,
                            const float* __restrict__ buh)
{
    const int idx = blockIdx.x * blockDim.x + threadIdx.x;
    const int total = BATCH * LEAF_CNT * MD;
    if (idx >= total) return;
    const int j = idx % MD;
    const int rn = idx / MD;
    const int node = LEAF_BASE + (rn & (LEAF_CNT - 1));
    const int b = rn >> 10;
    const size_t rowx = (size_t)b * NNODES + node;
    const float* gx = g_gates_x + rowx * 1200;
    const float i = sigmoidf(gx[j] + bih[j]);
    const float o = sigmoidf(gx[600 + j] + boh[j]);
    const float u = tanhf(gx[900 + j] + buh[j]);
    const float c = i * u;
    g_c[rowx * MD + j] = c;
    h[rowx * MD + j] = o * tanhf(c);
}

// -------------------- pointwise: internal level --------------------
__global__ void level_kernel(float* __restrict__ h, int l,
                             const float* __restrict__ bih,
                             const float* __restrict__ boh,
                             const float* __restrict__ buh,
                             const float* __restrict__ bfh)
{
    const int nl = 1 << l;
    const int Mh = BATCH << l;
    const int total = Mh * MD;
    const int idx = blockIdx.x * blockDim.x + threadIdx.x;
    if (idx >= total) return;
    const int j = idx % MD;
    const int r = idx / MD;
    const int t = r & (nl - 1);
    const int b = r >> l;
    const int node = (nl - 1) + t;
    const size_t rowx = (size_t)b * NNODES + node;
    const float* gx = g_gates_x + rowx * 1200;
    const float* gio = g_iou + (size_t)r * 900;

    const float i  = sigmoidf(gx[j]       + gio[j]       + bih[j]);
    const float o  = sigmoidf(gx[600 + j] + gio[300 + j] + boh[j]);
    const float u  = tanhf   (gx[900 + j] + gio[600 + j] + buh[j]);
    const float fx = gx[300 + j];
    const float f1 = sigmoidf(fx + g_f[(size_t)r * 300 + j] + bfh[j]);
    const float f2 = sigmoidf(fx + g_f[(size_t)(Mh + r) * 300 + j] + bfh[j]);

    const size_t row1 = (size_t)b * NNODES + 2 * node + 1;
    const size_t row2 = row1 + 1;
    const float cn = i * u + f1 * g_c[row1 * MD + j] + f2 * g_c[row2 * MD + j];
    g_c[rowx * MD + j] = cn;
    h[rowx * MD + j] = o * tanhf(cn);
}

// -------------------- host launch --------------------
extern "C" void kernel_launch(void* const* d_in, const int* in_sizes, int n_in,
                              void* d_out, int out_size)
{
    const float* embs = (const float*)d_in[0];
    const float* Wix = (const float*)d_in[1];
    const float* bix = (const float*)d_in[2];
    const float* Wih = (const float*)d_in[3];
    const float* bih = (const float*)d_in[4];
    const float* Wfx = (const float*)d_in[5];
    const float* bfx = (const float*)d_in[6];
    const float* Wfh = (const float*)d_in[7];
    const float* bfh = (const float*)d_in[8];
    const float* Wox = (const float*)d_in[9];
    const float* box_ = (const float*)d_in[10];
    const float* Woh = (const float*)d_in[11];
    const float* boh = (const float*)d_in[12];
    const float* Wux = (const float*)d_in[13];
    const float* bux = (const float*)d_in[14];
    const float* Wuh = (const float*)d_in[15];
    const float* buh = (const float*)d_in[16];
    float* h = (float*)d_out;

    float *gx_p, *c_p, *iou_p, *f_p, *Wx_p, *bx_p, *Wh_p;
    cudaGetSymbolAddress((void**)&gx_p, g_gates_x);
    cudaGetSymbolAddress((void**)&c_p, g_c);
    cudaGetSymbolAddress((void**)&iou_p, g_iou);
    cudaGetSymbolAddress((void**)&f_p, g_f);
    cudaGetSymbolAddress((void**)&Wx_p, g_Wx);
    cudaGetSymbolAddress((void**)&bx_p, g_bx);
    cudaGetSymbolAddress((void**)&Wh_p, g_Wh);
    (void)c_p; // referenced directly inside kernels

    // 1. pack weights
    pack_kernel<<<(300 * 1200 + 255) / 256, 256>>>(Wix, Wfx, Wox, Wux,
                                                   bix, bfx, box_, bux,
                                                   Wih, Woh, Wuh);

    // 2. input projection: gates_x = embs @ [Wix|Wfx|Wox|Wux] + b
    {
        dim3 grid((1200 + BN - 1) / BN, (TOTAL_ROWS + BM - 1) / BM);
        gemm_kernel<<<grid, 256>>>(embs, Wx_p, gx_p, bx_p,
                                   TOTAL_ROWS, 1200, 300,
                                   300, 1200, 1200, /*mode=*/0, 0);
    }

    // 3. leaves
    {
        const int total = BATCH * LEAF_CNT * MD;
        leaf_kernel<<<(total + 255) / 256, 256>>>(h, bih, boh, buh);
    }

    // 4. tree recursion, level 9 down to 0
    for (int l = DEPTH - 2; l >= 0; --l) {
        const int Mh = BATCH << l;
        {
            dim3 grid((900 + BN - 1) / BN, (Mh + BM - 1) / BM);
            gemm_kernel<<<grid, 256>>>(h, Wh_p, iou_p, nullptr,
                                       Mh, 900, 300,
                                       300, 900, 900, /*mode=*/1, l);
        }
        {
            dim3 grid((300 + BN - 1) / BN, (2 * Mh + BM - 1) / BM);
            gemm_kernel<<<grid, 256>>>(h, Wfh, f_p, nullptr,
                                       2 * Mh, 300, 300,
                                       300, 300, 300, /*mode=*/2, l);
        }
        {
            const int total = Mh * MD;
            level_kernel<<<(total + 255) / 256, 256>>>(h, l, bih, boh, buh, bfh);
        }
    }
}

// round 2
// speedup vs baseline: 1.5381x; 1.5381x over previous
#include <cuda_runtime.h>
#include <math.h>
#include <stdint.h>

// Problem constants
#define BATCH 32
#define DEPTH 11
#define NNODES 2047          // 2^11 - 1
#define IND 300
#define MD 300
#define LEAF_BASE 1023       // 2^10 - 1
#define LEAF_CNT 1024
#define TOTAL_ROWS (BATCH * NNODES)   // 65504

// GEMM tile config
#define BM 128
#define BN 128
#define BK 16
#define AS_LD 132            // padded lead dim for transposed A smem

typedef unsigned long long ull;

// -------------------- device scratch --------------------
__device__ float g_gates_x[(size_t)TOTAL_ROWS * 1200]; // [row][ix|fx|ox|ux]
__device__ float g_c[(size_t)TOTAL_ROWS * MD];
__device__ float g_iou[(size_t)(BATCH * 512) * 900];   // max level-9 rows x [ih|oh|uh]
__device__ float g_f[(size_t)(2 * BATCH * 512) * 300]; // stacked [f(h1); f(h2)]
__device__ float g_Wx[300 * 1200];
__device__ float g_bx[1200];
__device__ float g_Wh[300 * 900];

__device__ __forceinline__ float sigmoidf(float x) {
    return 1.0f / (1.0f + expf(-x));
}

// packed f32x2 helpers
__device__ __forceinline__ ull dup2(float x) {
    ull r; asm("mov.b64 %0, {%1, %1};" : "=l"(r) : "f"(x)); return r;
}
__device__ __forceinline__ void ffma2(ull& d, ull a, ull b) {
    asm("fma.rn.f32x2 %0, %1, %2, %0;" : "+l"(d) : "l"(a), "l"(b));
}
__device__ __forceinline__ float2 unpk(ull v) {
    float2 r; asm("mov.b64 {%0, %1}, %2;" : "=f"(r.x), "=f"(r.y) : "l"(v)); return r;
}
__device__ __forceinline__ void cp16(void* dst_smem, const void* src, bool pred) {
    uint32_t d = (uint32_t)__cvta_generic_to_shared(dst_smem);
    int sz = pred ? 16 : 0;
    asm volatile("cp.async.cg.shared.global [%0], [%1], 16, %2;" :: "r"(d), "l"(src), "r"(sz));
}
__device__ __forceinline__ void cp_commit() { asm volatile("cp.async.commit_group;"); }
__device__ __forceinline__ void cp_wait0() { asm volatile("cp.async.wait_group 0;"); }

// -------------------- weight packing --------------------
__global__ void pack_kernel(
    const float* __restrict__ Wix, const float* __restrict__ Wfx,
    const float* __restrict__ Wox, const float* __restrict__ Wux,
    const float* __restrict__ bix, const float* __restrict__ bfx,
    const float* __restrict__ box_, const float* __restrict__ bux,
    const float* __restrict__ Wih, const float* __restrict__ Woh,
    const float* __restrict__ Wuh)
{
    int i = blockIdx.x * blockDim.x + threadIdx.x;
    if (i < 300 * 1200) {
        int k = i / 1200, cj = i % 1200;
        int g = cj / 300, j = cj % 300;
        const float* W = (g == 0) ? Wix : (g == 1) ? Wfx : (g == 2) ? Wox : Wux;
        g_Wx[i] = W[k * 300 + j];
    }
    if (i < 1200) {
        int g = i / 300, j = i % 300;
        const float* bb = (g == 0) ? bix : (g == 1) ? bfx : (g == 2) ? box_ : bux;
        g_bx[i] = bb[j];
    }
    if (i < 300 * 900) {
        int k = i / 900, cj = i % 900;
        int g = cj / 300, j = cj % 300;
        const float* W = (g == 0) ? Wih : (g == 1) ? Woh : Wuh;
        g_Wh[i] = W[k * 300 + j];
    }
}

// -------------------- pipelined FFMA2 SGEMM with fused A-gather --------------------
// mode 0: A plain  (row r -> A + r*lda)
// mode 1: A = h[child1] + h[child2] for level `level_l` (A points at h base)
// mode 2: A = h[child1] for rows [0,Mh), h[child2] for rows [Mh,2Mh)
__global__ __launch_bounds__(256, 2) void gemm_kernel(
    const float* __restrict__ A, const float* __restrict__ Bm,
    float* __restrict__ C, const float* __restrict__ bias,
    int M, int N, int K, int lda, int ldb, int ldc,
    int mode, int level_l)
{
    __shared__ __align__(16) float As[2][BK][AS_LD];
    __shared__ __align__(16) float Bs[2][BK][BN];

    const int tid = threadIdx.x;
    const int m_base = blockIdx.y * BM;
    const int n_base = blockIdx.x * BN;

    // ---- A tile load mapping: thread -> (row am, k-half ak) ----
    const int am = tid >> 1;
    const int ak = (tid & 1) * 8;
    const float* arow1 = nullptr;
    const float* arow2 = nullptr;
    const int grow = m_base + am;
    const bool arow_ok = (grow < M);
    if (arow_ok) {
        if (mode == 0) {
            arow1 = A + (size_t)grow * lda;
        } else {
            const int nl = 1 << level_l;
            const int Mh = BATCH << level_l;
            int rr = grow, sel = 0;
            if (mode == 2 && grow >= Mh) { sel = 1; rr = grow - Mh; }
            const int b = rr >> level_l;
            const int t = rr & (nl - 1);
            const int node = (nl - 1) + t;
            if (mode == 1) {
                arow1 = A + ((size_t)b * NNODES + 2 * node + 1) * MD;
                arow2 = A + ((size_t)b * NNODES + 2 * node + 2) * MD;
            } else {
                arow1 = A + ((size_t)b * NNODES + 2 * node + 1 + sel) * MD;
            }
        }
    }

    // ---- B tile load mapping ----
    const int bk = tid >> 4;
    const int bn = (tid & 15) * 8;
    const bool nb0ok = (n_base + bn) < N;       // N is a multiple of 4
    const bool nb1ok = (n_base + bn + 4) < N;

    // ---- microtile mapping ----
    const int ty = tid >> 4, tx = tid & 15;
    const int mr = ty * 8, nr = tx * 8;

    ull acc[8][4];
#pragma unroll
    for (int i = 0; i < 8; i++)
#pragma unroll
        for (int j = 0; j < 4; j++) acc[i][j] = 0ULL;

    const int KT = (K + BK - 1) / BK;
    float av[8];

    // ---- A tile fetch into registers ----
    auto load_A = [&](int k0) {
        const int kk = k0 + ak;
        if (arow_ok && kk + 8 <= K) {
            float4 p = *(const float4*)(arow1 + kk);
            float4 q = *(const float4*)(arow1 + kk + 4);
            if (mode == 1) {
                float4 p2 = *(const float4*)(arow2 + kk);
                float4 q2 = *(const float4*)(arow2 + kk + 4);
                p.x += p2.x; p.y += p2.y; p.z += p2.z; p.w += p2.w;
                q.x += q2.x; q.y += q2.y; q.z += q2.z; q.w += q2.w;
            }
            av[0] = p.x; av[1] = p.y; av[2] = p.z; av[3] = p.w;
            av[4] = q.x; av[5] = q.y; av[6] = q.z; av[7] = q.w;
        } else if (arow_ok) {
#pragma unroll
            for (int j = 0; j < 8; j++) {
                const int k = kk + j;
                float v = 0.0f;
                if (k < K) {
                    v = __ldg(arow1 + k);
                    if (mode == 1) v += __ldg(arow2 + k);
                }
                av[j] = v;
            }
        } else {
#pragma unroll
            for (int j = 0; j < 8; j++) av[j] = 0.0f;
        }
    };
    auto store_A = [&](int sb) {
#pragma unroll
        for (int j = 0; j < 8; j++) As[sb][ak + j][am] = av[j];
    };
    auto load_B_async = [&](int k0, int sb) {
        const int kb = k0 + bk;
        const bool kv = kb < K;
        const float* bsrc = Bm + (size_t)kb * ldb + n_base + bn;
        cp16(&Bs[sb][bk][bn],     bsrc,     kv && nb0ok);
        cp16(&Bs[sb][bk][bn + 4], bsrc + 4, kv && nb1ok);
        cp_commit();
    };

    // ---- prologue: stage tile 0 ----
    load_B_async(0, 0);
    load_A(0);
    store_A(0);
    cp_wait0();
    __syncthreads();

    int s = 0;
    for (int t = 0; t < KT; ++t) {
        const bool has_next = (t + 1) < KT;
        if (has_next) {
            const int k0n = (t + 1) * BK;
            load_B_async(k0n, s ^ 1);
            load_A(k0n);
        }

        // ---- compute current stage ----
#pragma unroll
        for (int kk = 0; kk < BK; kk++) {
            const float4 a0 = *(const float4*)&As[s][kk][mr];
            const float4 a1 = *(const float4*)&As[s][kk][mr + 4];
            const double2 bq0 = *(const double2*)&Bs[s][kk][nr];
            const double2 bq1 = *(const double2*)&Bs[s][kk][nr + 4];
            ull b0 = __double_as_longlong(bq0.x);
            ull b1 = __double_as_longlong(bq0.y);
            ull b2 = __double_as_longlong(bq1.x);
            ull b3 = __double_as_longlong(bq1.y);
            float a[8] = {a0.x, a0.y, a0.z, a0.w, a1.x, a1.y, a1.z, a1.w};
#pragma unroll
            for (int i = 0; i < 8; i++) {
                const ull ad = dup2(a[i]);
                ffma2(acc[i][0], ad, b0);
                ffma2(acc[i][1], ad, b1);
                ffma2(acc[i][2], ad, b2);
                ffma2(acc[i][3], ad, b3);
            }
        }

        if (has_next) store_A(s ^ 1);
        cp_wait0();
        __syncthreads();
        s ^= 1;
    }

    // ---- epilogue ----
    const int gn0 = n_base + nr;
    float bvals[8];
#pragma unroll
    for (int j = 0; j < 8; j++)
        bvals[j] = (bias && gn0 + j < N) ? bias[gn0 + j] : 0.0f;

#pragma unroll
    for (int i = 0; i < 8; i++) {
        const int gm = m_base + mr + i;
        if (gm >= M) continue;
        float* crow = C + (size_t)gm * ldc + gn0;
        const float2 p0 = unpk(acc[i][0]);
        const float2 p1 = unpk(acc[i][1]);
        const float2 p2 = unpk(acc[i][2]);
        const float2 p3 = unpk(acc[i][3]);
        float4 v0 = make_float4(p0.x + bvals[0], p0.y + bvals[1],
                                p1.x + bvals[2], p1.y + bvals[3]);
        float4 v1 = make_float4(p2.x + bvals[4], p2.y + bvals[5],
                                p3.x + bvals[6], p3.y + bvals[7]);
        if (gn0 < N)     *(float4*)(crow)     = v0;   // N % 4 == 0
        if (gn0 + 4 < N) *(float4*)(crow + 4) = v1;
    }
}

// -------------------- pointwise: leaves --------------------
__global__ void leaf_kernel(float* __restrict__ h,
                            const float* __restrict__ bih,
                            const float* __restrict__ boh,
                            const float* __restrict__ buh)
{
    const int idx = blockIdx.x * blockDim.x + threadIdx.x;
    const int total = BATCH * LEAF_CNT * MD;
    if (idx >= total) return;
    const int j = idx % MD;
    const int rn = idx / MD;
    const int node = LEAF_BASE + (rn & (LEAF_CNT - 1));
    const int b = rn >> 10;
    const size_t rowx = (size_t)b * NNODES + node;
    const float* gx = g_gates_x + rowx * 1200;
    const float i = sigmoidf(gx[j] + bih[j]);
    const float o = sigmoidf(gx[600 + j] + boh[j]);
    const float u = tanhf(gx[900 + j] + buh[j]);
    const float c = i * u;
    g_c[rowx * MD + j] = c;
    h[rowx * MD + j] = o * tanhf(c);
}

// -------------------- pointwise: internal level --------------------
__global__ void level_kernel(float* __restrict__ h, int l,
                             const float* __restrict__ bih,
                             const float* __restrict__ boh,
                             const float* __restrict__ buh,
                             const float* __restrict__ bfh)
{
    const int nl = 1 << l;
    const int Mh = BATCH << l;
    const int total = Mh * MD;
    const int idx = blockIdx.x * blockDim.x + threadIdx.x;
    if (idx >= total) return;
    const int j = idx % MD;
    const int r = idx / MD;
    const int t = r & (nl - 1);
    const int b = r >> l;
    const int node = (nl - 1) + t;
    const size_t rowx = (size_t)b * NNODES + node;
    const float* gx = g_gates_x + rowx * 1200;
    const float* gio = g_iou + (size_t)r * 900;

    const float i  = sigmoidf(gx[j]       + gio[j]       + bih[j]);
    const float o  = sigmoidf(gx[600 + j] + gio[300 + j] + boh[j]);
    const float u  = tanhf   (gx[900 + j] + gio[600 + j] + buh[j]);
    const float fx = gx[300 + j];
    const float f1 = sigmoidf(fx + g_f[(size_t)r * 300 + j] + bfh[j]);
    const float f2 = sigmoidf(fx + g_f[(size_t)(Mh + r) * 300 + j] + bfh[j]);

    const size_t row1 = (size_t)b * NNODES + 2 * node + 1;
    const size_t row2 = row1 + 1;
    const float cn = i * u + f1 * g_c[row1 * MD + j] + f2 * g_c[row2 * MD + j];
    g_c[rowx * MD + j] = cn;
    h[rowx * MD + j] = o * tanhf(cn);
}

// -------------------- host launch --------------------
extern "C" void kernel_launch(void* const* d_in, const int* in_sizes, int n_in,
                              void* d_out, int out_size)
{
    const float* embs = (const float*)d_in[0];
    const float* Wix = (const float*)d_in[1];
    const float* bix = (const float*)d_in[2];
    const float* Wih = (const float*)d_in[3];
    const float* bih = (const float*)d_in[4];
    const float* Wfx = (const float*)d_in[5];
    const float* bfx = (const float*)d_in[6];
    const float* Wfh = (const float*)d_in[7];
    const float* bfh = (const float*)d_in[8];
    const float* Wox = (const float*)d_in[9];
    const float* box_ = (const float*)d_in[10];
    const float* Woh = (const float*)d_in[11];
    const float* boh = (const float*)d_in[12];
    const float* Wux = (const float*)d_in[13];
    const float* bux = (const float*)d_in[14];
    const float* Wuh = (const float*)d_in[15];
    const float* buh = (const float*)d_in[16];
    float* h = (float*)d_out;

    float *gx_p, *iou_p, *f_p, *Wx_p, *bx_p, *Wh_p;
    cudaGetSymbolAddress((void**)&gx_p, g_gates_x);
    cudaGetSymbolAddress((void**)&iou_p, g_iou);
    cudaGetSymbolAddress((void**)&f_p, g_f);
    cudaGetSymbolAddress((void**)&Wx_p, g_Wx);
    cudaGetSymbolAddress((void**)&bx_p, g_bx);
    cudaGetSymbolAddress((void**)&Wh_p, g_Wh);

    // 1. pack weights
    pack_kernel<<<(300 * 1200 + 255) / 256, 256>>>(Wix, Wfx, Wox, Wux,
                                                   bix, bfx, box_, bux,
                                                   Wih, Woh, Wuh);

    // 2. input projection: gates_x = embs @ [Wix|Wfx|Wox|Wux] + b
    {
        dim3 grid((1200 + BN - 1) / BN, (TOTAL_ROWS + BM - 1) / BM);
        gemm_kernel<<<grid, 256>>>(embs, Wx_p, gx_p, bx_p,
                                   TOTAL_ROWS, 1200, 300,
                                   300, 1200, 1200, /*mode=*/0, 0);
    }

    // 3. leaves
    {
        const int total = BATCH * LEAF_CNT * MD;
        leaf_kernel<<<(total + 255) / 256, 256>>>(h, bih, boh, buh);
    }

    // 4. tree recursion, level 9 down to 0
    for (int l = DEPTH - 2; l >= 0; --l) {
        const int Mh = BATCH << l;
        {
            dim3 grid((900 + BN - 1) / BN, (Mh + BM - 1) / BM);
            gemm_kernel<<<grid, 256>>>(h, Wh_p, iou_p, nullptr,
                                       Mh, 900, 300,
                                       300, 900, 900, /*mode=*/1, l);
        }
        {
            dim3 grid((300 + BN - 1) / BN, (2 * Mh + BM - 1) / BM);
            gemm_kernel<<<grid, 256>>>(h, Wfh, f_p, nullptr,
                                       2 * Mh, 300, 300,
                                       300, 300, 300, /*mode=*/2, l);
        }
        {
            const int total = Mh * MD;
            level_kernel<<<(total + 255) / 256, 256>>>(h, l, bih, boh, buh, bfh);
        }
    }
}

// round 4
// speedup vs baseline: 2.7497x; 1.7878x over previous
#include <cuda_runtime.h>
#include <cuda_bf16.h>
#include <math.h>
#include <stdint.h>

// ---------------- problem constants ----------------
#define BATCH 32
#define DEPTH 11
#define NNODES 2047
#define MD 300
#define KDIM 300
#define KPAD 320
#define KT 10                 // KPAD / 32 stages
#define LEAF_BASE 1023
#define LEAF_CNT 1024
#define TOTAL_ROWS (BATCH * NNODES)   // 65504
#define MAXSUM (BATCH * 512)          // 16384 max level rows

// ---------------- GEMM tile ----------------
#define BM 128
#define BN 128
// smem stage layout (bytes)
#define OFF_AHI 0
#define OFF_ALO 10240
#define OFF_BHI 20480
#define OFF_BLO 29184
#define STAGE_B 37888
#define SMEM_G (3 * STAGE_B)   // 113664

// padded N strides of packed weights
#define NP_X 1280
#define NP_H 1024
#define NP_F 384

typedef __nv_bfloat16 bf16;

// ---------------- device scratch ----------------
__device__ float g_gates_x[(size_t)TOTAL_ROWS * 1200];
__device__ float g_c[(size_t)TOTAL_ROWS * MD];
__device__ float g_iou[(size_t)MAXSUM * 900];
__device__ float g_f[(size_t)(2 * MAXSUM) * 300];
__device__ float g_bx[1200];

__device__ __align__(16) bf16 g_embh[(size_t)TOTAL_ROWS * KPAD];
__device__ __align__(16) bf16 g_embl[(size_t)TOTAL_ROWS * KPAD];
__device__ __align__(16) bf16 g_hh[(size_t)TOTAL_ROWS * KPAD];
__device__ __align__(16) bf16 g_hl[(size_t)TOTAL_ROWS * KPAD];
__device__ __align__(16) bf16 g_sumh[(size_t)MAXSUM * KPAD];
__device__ __align__(16) bf16 g_suml[(size_t)MAXSUM * KPAD];
__device__ __align__(16) bf16 g_Wxh[(size_t)KPAD * NP_X];
__device__ __align__(16) bf16 g_Wxl[(size_t)KPAD * NP_X];
__device__ __align__(16) bf16 g_Whh[(size_t)KPAD * NP_H];
__device__ __align__(16) bf16 g_Whl[(size_t)KPAD * NP_H];
__device__ __align__(16) bf16 g_Wfh[(size_t)KPAD * NP_F];
__device__ __align__(16) bf16 g_Wfl[(size_t)KPAD * NP_F];

__device__ __forceinline__ float sigmoidf(float x) {
    return 1.0f / (1.0f + expf(-x));
}
__device__ __forceinline__ void split_bf16(float v, bf16& hi, bf16& lo) {
    hi = __float2bfloat16(v);
    lo = __float2bfloat16(v - __bfloat162float(hi));
}

// ---------------- ptx helpers ----------------
__device__ __forceinline__ uint32_t smem_u32(const void* p) {
    uint32_t a;
    asm("{ .reg .u64 t; cvta.to.shared.u64 t, %1; cvt.u32.u64 %0, t; }" : "=r"(a) : "l"(p));
    return a;
}
__device__ __forceinline__ void cp16(uint32_t dst, const void* src, int sz) {
    asm volatile("cp.async.cg.shared.global [%0], [%1], 16, %2;"
                 :: "r"(dst), "l"(src), "r"(sz));
}
__device__ __forceinline__ void cp_commit() { asm volatile("cp.async.commit_group;"); }
__device__ __forceinline__ void ldsm4(unsigned* r, uint32_t a) {
    asm volatile("ldmatrix.sync.aligned.m8n8.x4.shared.b16 {%0,%1,%2,%3}, [%4];"
                 : "=r"(r[0]), "=r"(r[1]), "=r"(r[2]), "=r"(r[3]) : "r"(a));
}
__device__ __forceinline__ void ldsm4t(unsigned* r, uint32_t a) {
    asm volatile("ldmatrix.sync.aligned.m8n8.x4.trans.shared.b16 {%0,%1,%2,%3}, [%4];"
                 : "=r"(r[0]), "=r"(r[1]), "=r"(r[2]), "=r"(r[3]) : "r"(a));
}
__device__ __forceinline__ void mma16816(float* d, const unsigned* a, const unsigned* b) {
    asm volatile(
        "mma.sync.aligned.m16n8k16.row.col.f32.bf16.bf16.f32 "
        "{%0,%1,%2,%3}, {%4,%5,%6,%7}, {%8,%9}, {%0,%1,%2,%3};"
        : "+f"(d[0]), "+f"(d[1]), "+f"(d[2]), "+f"(d[3])
        : "r"(a[0]), "r"(a[1]), "r"(a[2]), "r"(a[3]), "r"(b[0]), "r"(b[1]));
}

// ---------------- weight packing: [k][n] bf16 hi/lo, padded, zero-filled ----------------
__global__ void pack_kernel(
    const float* __restrict__ Wix, const float* __restrict__ Wfx,
    const float* __restrict__ Wox, const float* __restrict__ Wux,
    const float* __restrict__ bix, const float* __restrict__ bfx,
    const float* __restrict__ box_, const float* __restrict__ bux,
    const float* __restrict__ Wih, const float* __restrict__ Woh,
    const float* __restrict__ Wuh, const float* __restrict__ Wfh)
{
    const int i = blockIdx.x * blockDim.x + threadIdx.x;
    if (i < KPAD * NP_X) {
        const int k = i / NP_X, n = i % NP_X;
        float v = 0.0f;
        if (k < KDIM && n < 1200) {
            const int g = n / 300, j = n % 300;
            const float* W = (g == 0) ? Wix : (g == 1) ? Wfx : (g == 2) ? Wox : Wux;
            v = W[k * 300 + j];
        }
        split_bf16(v, g_Wxh[i], g_Wxl[i]);
    }
    if (i < KPAD * NP_H) {
        const int k = i / NP_H, n = i % NP_H;
        float v = 0.0f;
        if (k < KDIM && n < 900) {
            const int g = n / 300, j = n % 300;
            const float* W = (g == 0) ? Wih : (g == 1) ? Woh : Wuh;
            v = W[k * 300 + j];
        }
        split_bf16(v, g_Whh[i], g_Whl[i]);
    }
    if (i < KPAD * NP_F) {
        const int k = i / NP_F, n = i % NP_F;
        float v = (k < KDIM && n < 300) ? Wfh[k * 300 + n] : 0.0f;
        split_bf16(v, g_Wfh[i], g_Wfl[i]);
    }
    if (i < 1200) {
        const int g = i / 300, j = i % 300;
        const float* bb = (g == 0) ? bix : (g == 1) ? bfx : (g == 2) ? box_ : bux;
        g_bx[i] = bb[j];
    }
}

// ---------------- embs -> bf16 hi/lo, padded ----------------
__global__ void convert_embs(const float* __restrict__ embs) {
    const long idx = (long)blockIdx.x * blockDim.x + threadIdx.x;
    if (idx >= (long)TOTAL_ROWS * KPAD) return;
    const long row = idx / KPAD;
    const int k = (int)(idx % KPAD);
    const float v = (k < KDIM) ? embs[row * KDIM + k] : 0.0f;
    split_bf16(v, g_embh[idx], g_embl[idx]);
}

// ---------------- per-level child-sum + split ----------------
__global__ void sumsplit_kernel(const float* __restrict__ h, int l) {
    const int nl = 1 << l;
    const int Mh = BATCH << l;
    const int total = Mh * MD;
    const int idx = blockIdx.x * blockDim.x + threadIdx.x;
    if (idx >= total) return;
    const int j = idx % MD;
    const int r = idx / MD;
    const int b = r >> l;
    const int t = r & (nl - 1);
    const int node = (nl - 1) + t;
    const size_t c1 = ((size_t)b * NNODES + 2 * node + 1) * MD;
    const float s = h[c1 + j] + h[c1 + MD + j];
    split_bf16(s, g_sumh[(size_t)r * KPAD + j], g_suml[(size_t)r * KPAD + j]);
}

// ---------------- bf16x3 HMMA GEMM with fused A-gather ----------------
// C[M,N] = A[M,KPAD] @ B[KPAD,N]  (A,B split hi/lo bf16; B row stride NP)
// mode 0: A row = grow * KPAD
// mode 2: A row = h split row of child(1 or 2) at level level_l (stacked)
__global__ __launch_bounds__(256, 1) void gemm_mma(
    const bf16* __restrict__ Ah, const bf16* __restrict__ Al,
    const bf16* __restrict__ Bh, const bf16* __restrict__ Bl,
    float* __restrict__ C, const float* __restrict__ bias,
    int M, int N, int NP, int ldc, int mode, int level_l)
{
    extern __shared__ __align__(128) char smem[];
    const uint32_t sbase = smem_u32(smem);
    const int tid = threadIdx.x;
    const int lane = tid & 31;
    const int wid = tid >> 5;
    const int wm = wid & 3;           // 4 m-warps * 32 rows
    const int wn = wid >> 2;          // 2 n-warps * 64 cols
    const int m_base = blockIdx.y * BM;
    const int n_base = blockIdx.x * BN;

    // ---- staging source offsets ----
    const int c4 = tid & 3;                 // A 16B chunk within 64B row-slab
    const int ar0 = tid >> 2;               // A rows: ar0, ar0+64
    size_t aoff[2]; int asz[2];
#pragma unroll
    for (int i = 0; i < 2; i++) {
        const int grow = m_base + ar0 + i * 64;
        const bool ok = grow < M;
        size_t off = 0;
        if (ok) {
            if (mode == 0) {
                off = (size_t)grow * KPAD;
            } else {
                const int nl = 1 << level_l;
                const int Mh = BATCH << level_l;
                int rr = grow, sel = 0;
                if (grow >= Mh) { sel = 1; rr -= Mh; }
                const int b = rr >> level_l;
                const int t = rr & (nl - 1);
                const int node = (nl - 1) + t;
                off = ((size_t)b * NNODES + 2 * node + 1 + sel) * KPAD;
            }
        }
        aoff[i] = off; asz[i] = ok ? 16 : 0;
    }
    const int cb = tid & 15;                // B 16B chunk (8 n) within 256B row
    const int br0 = tid >> 4;               // B k-rows: br0, br0+16
    const int bn0 = n_base + cb * 8;

    // ---- ldmatrix lane address components ----
    const uint32_t a_lane = (uint32_t)((lane & 15) * 80 + (lane >> 4) * 16);
    const int jj = lane >> 3, r8 = lane & 7;
    const uint32_t b_lane = (uint32_t)(((jj & 1) * 8 + r8) * 272 + (jj >> 1) * 16);

    float acc[2][8][4];
#pragma unroll
    for (int a = 0; a < 2; a++)
#pragma unroll
        for (int b = 0; b < 8; b++)
#pragma unroll
            for (int c = 0; c < 4; c++) acc[a][b][c] = 0.0f;

    // ---- stage helper ----
    auto stage = [&](int t, int buf) {
        const uint32_t sb = sbase + buf * STAGE_B;
        const int k0 = t * 32;
#pragma unroll
        for (int i = 0; i < 2; i++) {
            const int row = ar0 + i * 64;
            const size_t so = aoff[i] + k0 + c4 * 8;
            const uint32_t d = sb + row * 80 + c4 * 16;
            cp16(d + OFF_AHI, Ah + so, asz[i]);
            cp16(d + OFF_ALO, Al + so, asz[i]);
        }
#pragma unroll
        for (int i = 0; i < 2; i++) {
            const int kr = br0 + i * 16;
            const size_t so = (size_t)(k0 + kr) * NP + bn0;
            const uint32_t d = sb + kr * 272 + cb * 16;
            cp16(d + OFF_BHI, Bh + so, 16);
            cp16(d + OFF_BLO, Bl + so, 16);
        }
    };

    // ---- 3-stage pipeline ----
    stage(0, 0); cp_commit();
    stage(1, 1); cp_commit();

    for (int t = 0; t < KT; ++t) {
        asm volatile("cp.async.wait_group 1;" ::: "memory");
        __syncthreads();
        if (t + 2 < KT) stage(t + 2, (t + 2) % 3);
        cp_commit();

        const uint32_t sb = sbase + (t % 3) * STAGE_B;
#pragma unroll
        for (int k16 = 0; k16 < 2; k16++) {
            unsigned ah[2][4], al[2][4], bh[8][2], bl[8][2];
#pragma unroll
            for (int tm = 0; tm < 2; tm++) {
                const uint32_t ad = sb + (wm * 32 + tm * 16) * 80 + k16 * 32 + a_lane;
                ldsm4(ah[tm], ad + OFF_AHI);
                ldsm4(al[tm], ad + OFF_ALO);
            }
#pragma unroll
            for (int p = 0; p < 4; p++) {
                const uint32_t bd = sb + (uint32_t)(k16 * 16 * 272) +
                                    (uint32_t)((wn * 64 + p * 16) * 2) + b_lane;
                unsigned r[4];
                ldsm4t(r, bd + OFF_BHI);
                bh[2 * p][0] = r[0]; bh[2 * p][1] = r[1];
                bh[2 * p + 1][0] = r[2]; bh[2 * p + 1][1] = r[3];
                ldsm4t(r, bd + OFF_BLO);
                bl[2 * p][0] = r[0]; bl[2 * p][1] = r[1];
                bl[2 * p + 1][0] = r[2]; bl[2 * p + 1][1] = r[3];
            }
#pragma unroll
            for (int tm = 0; tm < 2; tm++)
#pragma unroll
                for (int tn = 0; tn < 8; tn++) {
                    mma16816(acc[tm][tn], ah[tm], bh[tn]);
                    mma16816(acc[tm][tn], ah[tm], bl[tn]);
                    mma16816(acc[tm][tn], al[tm], bh[tn]);
                }
        }
    }

    // ---- epilogue: registers -> C ----
    const int mrow = lane >> 2;
    const int ncol = (lane & 3) * 2;
#pragma unroll
    for (int tm = 0; tm < 2; tm++) {
#pragma unroll
        for (int half = 0; half < 2; half++) {
            const int gm = m_base + wm * 32 + tm * 16 + half * 8 + mrow;
            if (gm >= M) continue;
            float* crow = C + (size_t)gm * ldc;
#pragma unroll
            for (int tn = 0; tn < 8; tn++) {
                const int gn = n_base + wn * 64 + tn * 8 + ncol;
                if (gn < N) {
                    float v0 = acc[tm][tn][half * 2];
                    float v1 = acc[tm][tn][half * 2 + 1];
                    if (bias) { v0 += bias[gn]; v1 += bias[gn + 1]; }
                    crow[gn] = v0;
                    crow[gn + 1] = v1;
                }
            }
        }
    }
}

// ---------------- pointwise: leaves (+ h split) ----------------
__global__ void leaf_kernel(float* __restrict__ h,
                            const float* __restrict__ bih,
                            const float* __restrict__ boh,
                            const float* __restrict__ buh)
{
    const int idx = blockIdx.x * blockDim.x + threadIdx.x;
    const int total = BATCH * LEAF_CNT * MD;
    if (idx >= total) return;
    const int j = idx % MD;
    const int rn = idx / MD;
    const int node = LEAF_BASE + (rn & (LEAF_CNT - 1));
    const int b = rn >> 10;
    const size_t rowx = (size_t)b * NNODES + node;
    const float* gx = g_gates_x + rowx * 1200;
    const float i = sigmoidf(gx[j] + bih[j]);
    const float o = sigmoidf(gx[600 + j] + boh[j]);
    const float u = tanhf(gx[900 + j] + buh[j]);
    const float c = i * u;
    const float hv = o * tanhf(c);
    g_c[rowx * MD + j] = c;
    h[rowx * MD + j] = hv;
    split_bf16(hv, g_hh[rowx * KPAD + j], g_hl[rowx * KPAD + j]);
}

// ---------------- pointwise: internal level (+ h split) ----------------
__global__ void level_kernel(float* __restrict__ h, int l,
                             const float* __restrict__ bih,
                             const float* __restrict__ boh,
                             const float* __restrict__ buh,
                             const float* __restrict__ bfh)
{
    const int nl = 1 << l;
    const int Mh = BATCH << l;
    const int total = Mh * MD;
    const int idx = blockIdx.x * blockDim.x + threadIdx.x;
    if (idx >= total) return;
    const int j = idx % MD;
    const int r = idx / MD;
    const int t = r & (nl - 1);
    const int b = r >> l;
    const int node = (nl - 1) + t;
    const size_t rowx = (size_t)b * NNODES + node;
    const float* gx = g_gates_x + rowx * 1200;
    const float* gio = g_iou + (size_t)r * 900;

    const float i  = sigmoidf(gx[j]       + gio[j]       + bih[j]);
    const float o  = sigmoidf(gx[600 + j] + gio[300 + j] + boh[j]);
    const float u  = tanhf   (gx[900 + j] + gio[600 + j] + buh[j]);
    const float fx = gx[300 + j];
    const float f1 = sigmoidf(fx + g_f[(size_t)r * 300 + j] + bfh[j]);
    const float f2 = sigmoidf(fx + g_f[(size_t)(Mh + r) * 300 + j] + bfh[j]);

    const size_t row1 = (size_t)b * NNODES + 2 * node + 1;
    const float cn = i * u + f1 * g_c[row1 * MD + j] + f2 * g_c[(row1 + 1) * MD + j];
    const float hv = o * tanhf(cn);
    g_c[rowx * MD + j] = cn;
    h[rowx * MD + j] = hv;
    split_bf16(hv, g_hh[rowx * KPAD + j], g_hl[rowx * KPAD + j]);
}

// ---------------- host launch ----------------
extern "C" void kernel_launch(void* const* d_in, const int* in_sizes, int n_in,
                              void* d_out, int out_size)
{
    const float* embs = (const float*)d_in[0];
    const float* Wix = (const float*)d_in[1];
    const float* bix = (const float*)d_in[2];
    const float* Wih = (const float*)d_in[3];
    const float* bih = (const float*)d_in[4];
    const float* Wfx = (const float*)d_in[5];
    const float* bfx = (const float*)d_in[6];
    const float* Wfh = (const float*)d_in[7];
    const float* bfh = (const float*)d_in[8];
    const float* Wox = (const float*)d_in[9];
    const float* box_ = (const float*)d_in[10];
    const float* Woh = (const float*)d_in[11];
    const float* boh = (const float*)d_in[12];
    const float* Wux = (const float*)d_in[13];
    const float* bux = (const float*)d_in[14];
    const float* Wuh = (const float*)d_in[15];
    const float* buh = (const float*)d_in[16];
    float* h = (float*)d_out;

    cudaFuncSetAttribute(gemm_mma,
                         cudaFuncAttributeMaxDynamicSharedMemorySize, SMEM_G);

    float *gx_p, *iou_p, *f_p, *bx_p;
    bf16 *embh_p, *embl_p, *hh_p, *hl_p, *sumh_p, *suml_p;
    bf16 *Wxh_p, *Wxl_p, *Whh_p, *Whl_p, *Wfh_p, *Wfl_p;
    cudaGetSymbolAddress((void**)&gx_p, g_gates_x);
    cudaGetSymbolAddress((void**)&iou_p, g_iou);
    cudaGetSymbolAddress((void**)&f_p, g_f);
    cudaGetSymbolAddress((void**)&bx_p, g_bx);
    cudaGetSymbolAddress((void**)&embh_p, g_embh);
    cudaGetSymbolAddress((void**)&embl_p, g_embl);
    cudaGetSymbolAddress((void**)&hh_p, g_hh);
    cudaGetSymbolAddress((void**)&hl_p, g_hl);
    cudaGetSymbolAddress((void**)&sumh_p, g_sumh);
    cudaGetSymbolAddress((void**)&suml_p, g_suml);
    cudaGetSymbolAddress((void**)&Wxh_p, g_Wxh);
    cudaGetSymbolAddress((void**)&Wxl_p, g_Wxl);
    cudaGetSymbolAddress((void**)&Whh_p, g_Whh);
    cudaGetSymbolAddress((void**)&Whl_p, g_Whl);
    cudaGetSymbolAddress((void**)&Wfh_p, g_Wfh);
    cudaGetSymbolAddress((void**)&Wfl_p, g_Wfl);

    // 1. pack weights (bf16 hi/lo, padded) + bias
    pack_kernel<<<(KPAD * NP_X + 255) / 256, 256>>>(Wix, Wfx, Wox, Wux,
                                                    bix, bfx, box_, bux,
                                                    Wih, Woh, Wuh, Wfh);

    // 2. convert embeddings to bf16 hi/lo
    {
        const long total = (long)TOTAL_ROWS * KPAD;
        convert_embs<<<(int)((total + 255) / 256), 256>>>(embs);
    }

    // 3. input projection: gates_x = embs @ [Wix|Wfx|Wox|Wux] + b
    {
        dim3 grid(1200 / BN + ((1200 % BN) ? 1 : 0), (TOTAL_ROWS + BM - 1) / BM);
        gemm_mma<<<grid, 256, SMEM_G>>>(embh_p, embl_p, Wxh_p, Wxl_p,
                                        gx_p, bx_p,
                                        TOTAL_ROWS, 1200, NP_X, 1200, 0, 0);
    }

    // 4. leaves
    leaf_kernel<<<(BATCH * LEAF_CNT * MD + 255) / 256, 256>>>(h, bih, boh, buh);

    // 5. tree recursion
    for (int l = DEPTH - 2; l >= 0; --l) {
        const int Mh = BATCH << l;
        sumsplit_kernel<<<(Mh * MD + 255) / 256, 256>>>(h, l);
        {
            dim3 grid((900 + BN - 1) / BN, (Mh + BM - 1) / BM);
            gemm_mma<<<grid, 256, SMEM_G>>>(sumh_p, suml_p, Whh_p, Whl_p,
                                            iou_p, nullptr,
                                            Mh, 900, NP_H, 900, 0, 0);
        }
        {
            dim3 grid((300 + BN - 1) / BN, (2 * Mh + BM - 1) / BM);
            gemm_mma<<<grid, 256, SMEM_G>>>(hh_p, hl_p, Wfh_p, Wfl_p,
                                            f_p, nullptr,
                                            2 * Mh, 300, NP_F, 300, 2, l);
        }
        level_kernel<<<(Mh * MD + 255) / 256, 256>>>(h, l, bih, boh, buh, bfh);
    }
}